// round 5
// baseline (speedup 1.0000x reference)
#include <cuda_runtime.h>
#include <math.h>
#include <stdint.h>

// ---------------- problem constants ----------------
#define D_FULL   256
#define NHEAD    4
#define HDIM     64
#define NP       16
#define NM       32
#define NR       2
#define NB       1024
#define NL       128
#define NK       8
#define NNEG     2048
#define NPOS     (NB * NK)        /* 8192 */
#define NW       (NPOS + NNEG)    /* 10240 */
#define NUM_LABELS 131072
#define NF4      20               /* float4 feature groups per head: 4 poly + 16 prf */
#define QT       32               /* queries per score block */
#define NT       64               /* negs per score block */
#define NSPLIT   (NNEG / NT)      /* 32 */
#define WROWS    16               /* rows per w_feat block */
#define QROWS    8                /* rows per query block */

// ---------------- device scratch ----------------
__device__ float  g_anchT[HDIM * NP];        // normalized anchors, transposed [d][p]
__device__ float4 g_Q4[NHEAD * NF4 * NB];    // query feats  [(h*20+f4)*NB + b]
__device__ float4 g_W4[NHEAD * NF4 * NW];    // W feats      [(h*20+f4)*NW + row]
__device__ float  g_pos[NPOS];
__device__ float  g_Zpart[NSPLIT * NB];      // per-negsplit partial Z sums

// ---------------- anchors ----------------
__global__ void __launch_bounds__(256) anch_kernel(const float* __restrict__ anchors)
{
    __shared__ float inv[NP];
    int t = threadIdx.x;
    if (t < NP) {
        float s = 0.f;
        #pragma unroll 8
        for (int d = 0; d < HDIM; d++) {
            float v = anchors[t * HDIM + d];
            s = fmaf(v, v, s);
        }
        inv[t] = 1.f / sqrtf(s);
    }
    __syncthreads();
    for (int i = t; i < HDIM * NP; i += blockDim.x) {
        int p = i & (NP - 1);
        int d = i >> 4;
        g_anchT[i] = anchors[p * HDIM + d] * inv[p];
    }
}

// ---------------- per-row feature pipeline ----------------
// vcur = this thread's raw component (dim t of the 256-dim row).
// Global safe_normalize cancels under per-head normalize.
// om = this thread's omega column (64 regs). Writes float4-grouped layout.
__device__ __forceinline__ void process_row(
    float vcur, int t, int row, int nrows,
    float4* s_x4, float* s_ws, const float* s_anch,
    const float (&om)[HDIM], float4* outbase,
    float ss, float tt, float cc)
{
    // per-head L2 norm
    float sq = vcur * vcur;
    #pragma unroll
    for (int o = 16; o; o >>= 1) sq += __shfl_xor_sync(0xffffffffu, sq, o);
    if ((t & 31) == 0) s_ws[t >> 5] = sq;
    __syncthreads();
    int hq = t >> 6;
    float n = sqrtf(s_ws[2 * hq] + s_ws[2 * hq + 1]);
    ((float*)s_x4)[t] = vcur / fmaxf(n, 1e-20f);
    __syncthreads();

    // PRF feature: thread t -> (r, hh, m); omega dot from registers, x via LDS.128
    int r  = t >> 7;
    int hh = (t >> 5) & 3;
    int m  = t & 31;
    const float4* xh4 = s_x4 + hh * (HDIM / 4);
    float dotA = 0.f, dotB = 0.f;
    #pragma unroll
    for (int d4 = 0; d4 < HDIM / 4; d4++) {
        float4 x = xh4[d4];
        dotA = fmaf(x.x, om[4 * d4 + 0], dotA);
        dotB = fmaf(x.y, om[4 * d4 + 1], dotB);
        dotA = fmaf(x.z, om[4 * d4 + 2], dotA);
        dotB = fmaf(x.w, om[4 * d4 + 3], dotB);
    }
    float dot = (dotA + dotB) * 0.125f;            // omega / sqrt(64)
    float arg = fminf(fmaxf(dot * tt - ss, -20.f), 20.f);
    float pf  = expf(arg) * cc;
    int f = 16 + r * NM + m;                       // within-head feature index
    ((float*)outbase)[(((size_t)(hh * NF4 + (f >> 2))) * nrows + row) * 4 + (f & 3)] = pf;

    // poly feature: threads 0..63 -> (h2, p)
    if (t < 64) {
        int h2 = t >> 4, p = t & 15;
        const float* xh2 = (const float*)s_x4 + h2 * HDIM;
        float d2 = 0.f, d2b = 0.f;
        #pragma unroll
        for (int d = 0; d < HDIM; d += 2) {
            d2  = fmaf(xh2[d],     s_anch[d * NP + p],       d2);
            d2b = fmaf(xh2[d + 1], s_anch[(d + 1) * NP + p], d2b);
        }
        d2 += d2b;
        d2 = fminf(fmaxf(d2, -1.f), 1.f);
        ((float*)outbase)[(((size_t)(h2 * NF4 + (p >> 2))) * nrows + row) * 4 + (p & 3)] = d2 * d2 * 0.25f;
    }
    __syncthreads();   // protect s_x/s_ws before next row overwrites
}

// ---------------- queries: gather+sum embeddings, then features ----------------
__global__ void __launch_bounds__(256) query_feat_kernel(
    const int* __restrict__ indices, const float* __restrict__ mask,
    const float* __restrict__ etab, const float* __restrict__ omega,
    float s0, float s1, float t0, float t1, float c0, float c1)
{
    __shared__ float4 s_x4[HDIM];
    __shared__ float  s_ws[8];
    __shared__ float  s_anch[HDIM * NP];
    __shared__ int    s_i[NL];
    __shared__ float  s_m[NL];
    int t = threadIdx.x;
    int r = t >> 7, hh = (t >> 5) & 3, m = t & 31;

    float om[HDIM];
    const float* omp = omega + ((size_t)(r * NHEAD + hh) * HDIM) * NM + m;
    #pragma unroll
    for (int d = 0; d < HDIM; d++) om[d] = omp[d * NM];
    for (int i = t; i < HDIM * NP; i += 256) s_anch[i] = g_anchT[i];
    float ss = r ? s1 : s0, tt = r ? t1 : t0, cc = r ? c1 : c0;

    int b0 = blockIdx.x * QROWS;
    for (int rr = 0; rr < QROWS; rr++) {
        int b = b0 + rr;
        if (t < NL) { s_i[t] = indices[b * NL + t]; s_m[t] = mask[b * NL + t]; }
        __syncthreads();
        float acc = 0.f;
        #pragma unroll 4
        for (int l = 0; l < NL; l++)
            acc = fmaf(s_m[l], etab[(size_t)s_i[l] * D_FULL + t], acc);
        // division by max(sum mask,1) cancels in per-head normalize
        process_row(acc, t, b, NB, s_x4, s_ws, s_anch, om, g_Q4, ss, tt, cc);
    }
}

// ---------------- W subset: gather kernel columns, then features ----------------
__global__ void __launch_bounds__(256) w_feat_kernel(
    const int* __restrict__ labels, const int* __restrict__ neg_idx,
    const float* __restrict__ kern, const float* __restrict__ omega,
    float s0, float s1, float t0, float t1, float c0, float c1)
{
    __shared__ float4 s_x4[HDIM];
    __shared__ float  s_ws[8];
    __shared__ float  s_anch[HDIM * NP];
    int t = threadIdx.x;
    int r = t >> 7, hh = (t >> 5) & 3, m = t & 31;

    float om[HDIM];
    const float* omp = omega + ((size_t)(r * NHEAD + hh) * HDIM) * NM + m;
    #pragma unroll
    for (int d = 0; d < HDIM; d++) om[d] = omp[d * NM];
    for (int i = t; i < HDIM * NP; i += 256) s_anch[i] = g_anchT[i];
    float ss = r ? s1 : s0, tt = r ? t1 : t0, cc = r ? c1 : c0;

    int row0 = blockIdx.x * WROWS;
    int c0i = (row0 < NPOS) ? (labels[row0] < 0 ? 0 : labels[row0]) : neg_idx[row0 - NPOS];
    float v = kern[(size_t)t * NUM_LABELS + c0i];
    __syncthreads();

    for (int rr = 0; rr < WROWS; rr++) {
        int row = row0 + rr;
        float vcur = v;
        if (rr + 1 < WROWS) {            // prefetch next gather
            int nr = row + 1;
            int c2 = (nr < NPOS) ? (labels[nr] < 0 ? 0 : labels[nr]) : neg_idx[nr - NPOS];
            v = kern[(size_t)t * NUM_LABELS + c2];
        }
        process_row(vcur, t, row, NW, s_x4, s_ws, s_anch, om, g_W4, ss, tt, cc);
    }
}

// ---------------- positives: one thread per (b,k) pair, coalesced float4 ----------------
__global__ void __launch_bounds__(256) pos_kernel()
{
    int rrow = blockIdx.x * 256 + threadIdx.x;   // 0..8191
    int q = rrow >> 3;
    float acc = 0.f;
    #pragma unroll 1
    for (int h = 0; h < NHEAD; h++) {
        float dP = 0.f;
        #pragma unroll
        for (int f4 = 0; f4 < 4; f4++) {
            float4 w  = g_W4[(size_t)(h * NF4 + f4) * NW + rrow];
            float4 qv = g_Q4[(size_t)(h * NF4 + f4) * NB + q];
            dP = fmaf(qv.x, w.x, fmaf(qv.y, w.y, fmaf(qv.z, w.z, fmaf(qv.w, w.w, dP))));
        }
        float dR = 0.f;
        #pragma unroll 4
        for (int f4 = 4; f4 < NF4; f4++) {
            float4 w  = g_W4[(size_t)(h * NF4 + f4) * NW + rrow];
            float4 qv = g_Q4[(size_t)(h * NF4 + f4) * NB + q];
            dR = fmaf(qv.x, w.x, fmaf(qv.y, w.y, fmaf(qv.z, w.z, fmaf(qv.w, w.w, dR))));
        }
        acc = fmaf(dP, dR, acc);
    }
    g_pos[rrow] = acc;
}

// ---------------- negatives: register-tiled score kernel ----------------
// Block tile 32q x 64n, thread tile 4q x 2n. Warp g owns queries 4g..4g+3
// (Q reads broadcast); lanes own consecutive negs (W LDS.128 conflict-free).
__global__ void __launch_bounds__(256) score_neg_kernel()
{
    __shared__ float4 sW[NF4 * NT];   // 20 KB, [f4][n]
    __shared__ float4 sQ[NF4 * QT];   // 10 KB, [f4][q]
    int t  = threadIdx.x;
    int qb = blockIdx.x * QT;
    int n0 = NPOS + blockIdx.y * NT;
    int g  = t >> 5;                  // warp id = query group
    int tn = t & 31;

    float acc[4][2] = {};
    #pragma unroll 1
    for (int h = 0; h < NHEAD; h++) {
        for (int i = t; i < NF4 * NT; i += 256)
            sW[i] = g_W4[(size_t)(h * NF4 + (i >> 6)) * NW + n0 + (i & 63)];
        for (int i = t; i < NF4 * QT; i += 256)
            sQ[i] = g_Q4[(size_t)(h * NF4 + (i >> 5)) * NB + qb + (i & 31)];
        __syncthreads();

        float dP[4][2] = {}, dR[4][2] = {};
        #pragma unroll
        for (int f4 = 0; f4 < 4; f4++) {
            float4 w0 = sW[f4 * NT + tn];
            float4 w1 = sW[f4 * NT + tn + 32];
            #pragma unroll
            for (int i = 0; i < 4; i++) {
                float4 q = sQ[f4 * QT + g * 4 + i];
                dP[i][0] = fmaf(q.x, w0.x, fmaf(q.y, w0.y, fmaf(q.z, w0.z, fmaf(q.w, w0.w, dP[i][0]))));
                dP[i][1] = fmaf(q.x, w1.x, fmaf(q.y, w1.y, fmaf(q.z, w1.z, fmaf(q.w, w1.w, dP[i][1]))));
            }
        }
        #pragma unroll 4
        for (int f4 = 4; f4 < NF4; f4++) {
            float4 w0 = sW[f4 * NT + tn];
            float4 w1 = sW[f4 * NT + tn + 32];
            #pragma unroll
            for (int i = 0; i < 4; i++) {
                float4 q = sQ[f4 * QT + g * 4 + i];
                dR[i][0] = fmaf(q.x, w0.x, fmaf(q.y, w0.y, fmaf(q.z, w0.z, fmaf(q.w, w0.w, dR[i][0]))));
                dR[i][1] = fmaf(q.x, w1.x, fmaf(q.y, w1.y, fmaf(q.z, w1.z, fmaf(q.w, w1.w, dR[i][1]))));
            }
        }
        #pragma unroll
        for (int i = 0; i < 4; i++) {
            acc[i][0] = fmaf(dP[i][0], dR[i][0], acc[i][0]);
            acc[i][1] = fmaf(dP[i][1], dR[i][1], acc[i][1]);
        }
        __syncthreads();
    }

    // per-warp reduce over this warp's 64 negs; warp owns its 4 queries exclusively
    float z[4];
    #pragma unroll
    for (int i = 0; i < 4; i++) z[i] = acc[i][0] + acc[i][1];
    #pragma unroll
    for (int o = 16; o; o >>= 1) {
        z[0] += __shfl_xor_sync(0xffffffffu, z[0], o);
        z[1] += __shfl_xor_sync(0xffffffffu, z[1], o);
        z[2] += __shfl_xor_sync(0xffffffffu, z[2], o);
        z[3] += __shfl_xor_sync(0xffffffffu, z[3], o);
    }
    if (tn == 0) {
        #pragma unroll
        for (int i = 0; i < 4; i++)
            g_Zpart[blockIdx.y * NB + qb + g * 4 + i] = z[i];
    }
}

// ---------------- final loss reduction ----------------
__global__ void __launch_bounds__(1024) loss_kernel(const float* __restrict__ label_mask,
                                                    float* __restrict__ out)
{
    int t = threadIdx.x;  // t == b
    // Z_b = sum pos + sum negs + 2056 * 1e-8  (logsumexp(log x) == log(sum x))
    float Z = 2056.f * 1e-8f;
    #pragma unroll 8
    for (int ns = 0; ns < NSPLIT; ns++) Z += g_Zpart[ns * NB + t];
    float ps[NK];
    #pragma unroll
    for (int k = 0; k < NK; k++) { ps[k] = g_pos[t * NK + k]; Z += ps[k]; }
    float lz = logf(Z);
    float num = 0.f, den = 0.f;
    #pragma unroll
    for (int k = 0; k < NK; k++) {
        float lm = label_mask[t * NK + k];
        float p  = ps[k] + 1e-8f;
        num += lm * (logf(fmaxf(p, 1e-8f)) - lz);
        den += lm;
    }
    __shared__ float sn[32], sd[32];
    #pragma unroll
    for (int o = 16; o; o >>= 1) {
        num += __shfl_xor_sync(0xffffffffu, num, o);
        den += __shfl_xor_sync(0xffffffffu, den, o);
    }
    if ((t & 31) == 0) { sn[t >> 5] = num; sd[t >> 5] = den; }
    __syncthreads();
    if (t < 32) {
        num = sn[t]; den = sd[t];
        #pragma unroll
        for (int o = 16; o; o >>= 1) {
            num += __shfl_xor_sync(0xffffffffu, num, o);
            den += __shfl_xor_sync(0xffffffffu, den, o);
        }
        if (t == 0) out[0] = -num / (den + 1e-6f);
    }
}

// ---------------- launch ----------------
extern "C" void kernel_launch(void* const* d_in, const int* in_sizes, int n_in,
                              void* d_out, int out_size)
{
    const int*   indices    = (const int*)  d_in[0];
    const float* mask       = (const float*)d_in[1];
    const int*   labels     = (const int*)  d_in[2];
    const float* label_mask = (const float*)d_in[3];
    const int*   neg_idx    = (const int*)  d_in[4];
    const float* etab       = (const float*)d_in[5];
    const float* kern       = (const float*)d_in[6];
    const float* omega      = (const float*)d_in[7];
    const float* anchors    = (const float*)d_in[8];
    float* out = (float*)d_out;

    // Gauss-Laguerre(2) constants, matching reference fp pairing
    const double Cc = 2.0 + 1e-6;
    const double r2 = 1.4142135623730951;
    float s0 = (float)((2.0 - r2) / Cc);
    float s1 = (float)((2.0 + r2) / Cc);
    float t0 = sqrtf(2.0f * s0);
    float t1 = sqrtf(2.0f * s1);
    float w0 = (float)(((2.0 + r2) / 4.0) / Cc);
    float w1 = (float)(((2.0 - r2) / 4.0) / Cc);
    float invM = 1.0f / sqrtf(32.0f + 1e-6f);
    float c0 = sqrtf(fmaxf(w0, 1e-6f)) * invM;
    float c1 = sqrtf(fmaxf(w1, 1e-6f)) * invM;

    anch_kernel<<<1, 256>>>(anchors);
    query_feat_kernel<<<NB / QROWS, 256>>>(indices, mask, etab, omega, s0, s1, t0, t1, c0, c1);
    w_feat_kernel<<<NW / WROWS, 256>>>(labels, neg_idx, kern, omega, s0, s1, t0, t1, c0, c1);
    pos_kernel<<<NPOS / 256, 256>>>();
    {
        dim3 grid(NB / QT, NSPLIT);
        score_neg_kernel<<<grid, 256>>>();
    }
    loss_kernel<<<1, NB>>>(label_mask, out);
}

// round 6
// speedup vs baseline: 1.3348x; 1.3348x over previous
#include <cuda_runtime.h>
#include <math.h>
#include <stdint.h>

// ---------------- problem constants ----------------
#define D_FULL   256
#define NHEAD    4
#define HDIM     64
#define NP       16
#define NM       32
#define NR       2
#define NB       1024
#define NL       128
#define NK       8
#define NNEG     2048
#define NPOS     (NB * NK)        /* 8192 */
#define NW       (NPOS + NNEG)    /* 10240 */
#define NUM_LABELS 131072
#define NF4      20               /* float4 feature groups per head: 4 poly + 16 prf */
#define QT       32               /* queries per score block */
#define NT       128              /* negs per score block */
#define NSPLIT   (NNEG / NT)      /* 16 */
#define WROWS    8                /* rows per w_feat block */

// ---------------- device scratch ----------------
__device__ float  g_anchT[HDIM * NP];        // normalized anchors, transposed [d][p]
__device__ float4 g_Q4[NHEAD * NF4 * NB];    // query feats  [(h*20+f4)*NB + b]
__device__ float4 g_W4[NHEAD * NF4 * NW];    // W feats      [(h*20+f4)*NW + row]
__device__ float  g_pos[NPOS];
__device__ float  g_Zpart[NSPLIT * NB];      // per-negsplit partial Z sums

// ---------------- anchors ----------------
__global__ void __launch_bounds__(256) anch_kernel(const float* __restrict__ anchors)
{
    __shared__ float inv[NP];
    int t = threadIdx.x;
    if (t < NP) {
        float s = 0.f;
        #pragma unroll 8
        for (int d = 0; d < HDIM; d++) {
            float v = anchors[t * HDIM + d];
            s = fmaf(v, v, s);
        }
        inv[t] = 1.f / sqrtf(s);
    }
    __syncthreads();
    for (int i = t; i < HDIM * NP; i += blockDim.x) {
        int p = i & (NP - 1);
        int d = i >> 4;
        g_anchT[i] = anchors[p * HDIM + d] * inv[p];
    }
}

// ---------------- per-row feature pipeline ----------------
// vcur = raw component for dim t. Global safe_normalize cancels under the
// per-head normalize. om = this thread's omega column (64 regs).
__device__ __forceinline__ void process_row(
    float vcur, int t, int row, int nrows,
    float4* s_x4, float* s_ws, const float* s_anch,
    const float (&om)[HDIM], float4* outbase,
    float ss, float tt, float cc)
{
    float sq = vcur * vcur;
    #pragma unroll
    for (int o = 16; o; o >>= 1) sq += __shfl_xor_sync(0xffffffffu, sq, o);
    if ((t & 31) == 0) s_ws[t >> 5] = sq;
    __syncthreads();
    int hq = t >> 6;
    float n = sqrtf(s_ws[2 * hq] + s_ws[2 * hq + 1]);
    ((float*)s_x4)[t] = vcur / fmaxf(n, 1e-20f);
    __syncthreads();

    // PRF feature: thread t -> (r, hh, m)
    int r  = t >> 7;
    int hh = (t >> 5) & 3;
    int m  = t & 31;
    const float4* xh4 = s_x4 + hh * (HDIM / 4);
    float dotA = 0.f, dotB = 0.f;
    #pragma unroll
    for (int d4 = 0; d4 < HDIM / 4; d4++) {
        float4 x = xh4[d4];
        dotA = fmaf(x.x, om[4 * d4 + 0], dotA);
        dotB = fmaf(x.y, om[4 * d4 + 1], dotB);
        dotA = fmaf(x.z, om[4 * d4 + 2], dotA);
        dotB = fmaf(x.w, om[4 * d4 + 3], dotB);
    }
    float dot = (dotA + dotB) * 0.125f;            // omega / sqrt(64)
    float arg = fminf(fmaxf(dot * tt - ss, -20.f), 20.f);
    float pf  = expf(arg) * cc;
    int f = 16 + r * NM + m;                       // within-head feature index
    ((float*)outbase)[(((size_t)(hh * NF4 + (f >> 2))) * nrows + row) * 4 + (f & 3)] = pf;

    // poly feature: threads 0..63 -> (h2, p)
    if (t < 64) {
        int h2 = t >> 4, p = t & 15;
        const float* xh2 = (const float*)s_x4 + h2 * HDIM;
        float d2 = 0.f, d2b = 0.f;
        #pragma unroll
        for (int d = 0; d < HDIM; d += 2) {
            d2  = fmaf(xh2[d],     s_anch[d * NP + p],       d2);
            d2b = fmaf(xh2[d + 1], s_anch[(d + 1) * NP + p], d2b);
        }
        d2 += d2b;
        d2 = fminf(fmaxf(d2, -1.f), 1.f);
        ((float*)outbase)[(((size_t)(h2 * NF4 + (p >> 2))) * nrows + row) * 4 + (p & 3)] = d2 * d2 * 0.25f;
    }
    __syncthreads();
}

// ---------------- queries: one block per query row ----------------
__global__ void __launch_bounds__(256) query_feat_kernel(
    const int* __restrict__ indices, const float* __restrict__ mask,
    const float* __restrict__ etab, const float* __restrict__ omega,
    float s0, float s1, float t0, float t1, float c0, float c1)
{
    __shared__ float4 s_x4[HDIM];
    __shared__ float  s_ws[8];
    __shared__ float  s_anch[HDIM * NP];
    __shared__ int    s_i[NL];
    __shared__ float  s_m[NL];
    int t = threadIdx.x, b = blockIdx.x;
    int r = t >> 7, hh = (t >> 5) & 3, m = t & 31;

    float om[HDIM];
    const float* omp = omega + ((size_t)(r * NHEAD + hh) * HDIM) * NM + m;
    #pragma unroll
    for (int d = 0; d < HDIM; d++) om[d] = omp[d * NM];
    for (int i = t; i < HDIM * NP; i += 256) s_anch[i] = g_anchT[i];
    float ss = r ? s1 : s0, tt = r ? t1 : t0, cc = r ? c1 : c0;

    if (t < NL) { s_i[t] = indices[b * NL + t]; s_m[t] = mask[b * NL + t]; }
    __syncthreads();
    float acc = 0.f;
    #pragma unroll 8
    for (int l = 0; l < NL; l++)
        acc = fmaf(s_m[l], etab[(size_t)s_i[l] * D_FULL + t], acc);
    // division by max(sum mask,1) cancels in per-head normalize
    process_row(acc, t, b, NB, s_x4, s_ws, s_anch, om, g_Q4, ss, tt, cc);
}

// ---------------- W subset: 8 rows per block, gather prefetch ----------------
__global__ void __launch_bounds__(256) w_feat_kernel(
    const int* __restrict__ labels, const int* __restrict__ neg_idx,
    const float* __restrict__ kern, const float* __restrict__ omega,
    float s0, float s1, float t0, float t1, float c0, float c1)
{
    __shared__ float4 s_x4[HDIM];
    __shared__ float  s_ws[8];
    __shared__ float  s_anch[HDIM * NP];
    int t = threadIdx.x;
    int r = t >> 7, hh = (t >> 5) & 3, m = t & 31;

    float om[HDIM];
    const float* omp = omega + ((size_t)(r * NHEAD + hh) * HDIM) * NM + m;
    #pragma unroll
    for (int d = 0; d < HDIM; d++) om[d] = omp[d * NM];
    for (int i = t; i < HDIM * NP; i += 256) s_anch[i] = g_anchT[i];
    float ss = r ? s1 : s0, tt = r ? t1 : t0, cc = r ? c1 : c0;

    int row0 = blockIdx.x * WROWS;
    int c0i = (row0 < NPOS) ? (labels[row0] < 0 ? 0 : labels[row0]) : neg_idx[row0 - NPOS];
    float v = kern[(size_t)t * NUM_LABELS + c0i];
    __syncthreads();

    for (int rr = 0; rr < WROWS; rr++) {
        int row = row0 + rr;
        float vcur = v;
        if (rr + 1 < WROWS) {
            int nr = row + 1;
            int c2 = (nr < NPOS) ? (labels[nr] < 0 ? 0 : labels[nr]) : neg_idx[nr - NPOS];
            v = kern[(size_t)t * NUM_LABELS + c2];
        }
        process_row(vcur, t, row, NW, s_x4, s_ws, s_anch, om, g_W4, ss, tt, cc);
    }
}

// ---------------- positives: 4 threads per row (one per head) ----------------
__global__ void __launch_bounds__(256) pos_kernel()
{
    int t = threadIdx.x;
    int lane = t & 31;
    int rowoff = lane & 7;                 // 8 consecutive rows per lane-group
    int h = lane >> 3;                     // head per lane-group
    int rowbase = blockIdx.x * 64 + (t >> 5) * 8;
    int rrow = rowbase + rowoff;
    int q = rrow >> 3;                     // == rowbase>>3, warp-segment uniform

    float dP = 0.f;
    #pragma unroll
    for (int f4 = 0; f4 < 4; f4++) {
        float4 w  = g_W4[(size_t)(h * NF4 + f4) * NW + rrow];
        float4 qv = g_Q4[(size_t)(h * NF4 + f4) * NB + q];
        dP = fmaf(qv.x, w.x, fmaf(qv.y, w.y, fmaf(qv.z, w.z, fmaf(qv.w, w.w, dP))));
    }
    float dR = 0.f;
    #pragma unroll 8
    for (int f4 = 4; f4 < NF4; f4++) {
        float4 w  = g_W4[(size_t)(h * NF4 + f4) * NW + rrow];
        float4 qv = g_Q4[(size_t)(h * NF4 + f4) * NB + q];
        dR = fmaf(qv.x, w.x, fmaf(qv.y, w.y, fmaf(qv.z, w.z, fmaf(qv.w, w.w, dR))));
    }
    float acc = dP * dR;
    acc += __shfl_xor_sync(0xffffffffu, acc, 8);
    acc += __shfl_xor_sync(0xffffffffu, acc, 16);
    if (lane < 8) g_pos[rrow] = acc;
}

// ---------------- negatives: register-tiled 32q x 128n, thread tile 4x4 ----------------
__global__ void __launch_bounds__(256) score_neg_kernel()
{
    __shared__ float4 sW[NF4 * NT];   // 40 KB  [f4][n]
    __shared__ float4 sQ[NF4 * QT];   // 10 KB  [f4][q]
    int t  = threadIdx.x;
    int qb = blockIdx.x * QT;
    int n0 = NPOS + blockIdx.y * NT;
    int g  = t >> 5;                  // warp -> 4 queries
    int tn = t & 31;                  // lane -> negs {tn, tn+32, tn+64, tn+96}

    float acc[4][4] = {};
    #pragma unroll 1
    for (int h = 0; h < NHEAD; h++) {
        for (int i = t; i < NF4 * NT; i += 256)
            sW[i] = g_W4[(size_t)(h * NF4 + (i >> 7)) * NW + n0 + (i & 127)];
        if (t < NF4 * QT - 512) sQ[512 + t] = g_Q4[(size_t)(h * NF4 + ((512 + t) >> 5)) * NB + qb + (t & 31)];
        sQ[t] = g_Q4[(size_t)(h * NF4 + (t >> 5)) * NB + qb + (t & 31)];
        sQ[256 + t] = g_Q4[(size_t)(h * NF4 + ((256 + t) >> 5)) * NB + qb + (t & 31)];
        __syncthreads();

        float dP[4][4] = {}, dR[4][4] = {};
        #pragma unroll
        for (int f4 = 0; f4 < 4; f4++) {
            float4 w[4];
            #pragma unroll
            for (int j = 0; j < 4; j++) w[j] = sW[f4 * NT + tn + 32 * j];
            #pragma unroll
            for (int i = 0; i < 4; i++) {
                float4 q = sQ[f4 * QT + g * 4 + i];
                #pragma unroll
                for (int j = 0; j < 4; j++)
                    dP[i][j] = fmaf(q.x, w[j].x, fmaf(q.y, w[j].y, fmaf(q.z, w[j].z, fmaf(q.w, w[j].w, dP[i][j]))));
            }
        }
        #pragma unroll 4
        for (int f4 = 4; f4 < NF4; f4++) {
            float4 w[4];
            #pragma unroll
            for (int j = 0; j < 4; j++) w[j] = sW[f4 * NT + tn + 32 * j];
            #pragma unroll
            for (int i = 0; i < 4; i++) {
                float4 q = sQ[f4 * QT + g * 4 + i];
                #pragma unroll
                for (int j = 0; j < 4; j++)
                    dR[i][j] = fmaf(q.x, w[j].x, fmaf(q.y, w[j].y, fmaf(q.z, w[j].z, fmaf(q.w, w[j].w, dR[i][j]))));
            }
        }
        #pragma unroll
        for (int i = 0; i < 4; i++)
            #pragma unroll
            for (int j = 0; j < 4; j++)
                acc[i][j] = fmaf(dP[i][j], dR[i][j], acc[i][j]);
        __syncthreads();
    }

    // warp owns its 4 queries exclusively: reduce 128 negs per query
    #pragma unroll
    for (int i = 0; i < 4; i++) {
        float z = (acc[i][0] + acc[i][1]) + (acc[i][2] + acc[i][3]);
        #pragma unroll
        for (int o = 16; o; o >>= 1) z += __shfl_xor_sync(0xffffffffu, z, o);
        if (tn == 0) g_Zpart[blockIdx.y * NB + qb + g * 4 + i] = z;
    }
}

// ---------------- final loss reduction ----------------
__global__ void __launch_bounds__(1024) loss_kernel(const float* __restrict__ label_mask,
                                                    float* __restrict__ out)
{
    int t = threadIdx.x;  // t == b
    // Z_b = sum pos + sum negs + 2056*1e-8  (logsumexp(log x) == log(sum x))
    float Z = 2056.f * 1e-8f;
    #pragma unroll
    for (int ns = 0; ns < NSPLIT; ns++) Z += g_Zpart[ns * NB + t];
    float ps[NK];
    #pragma unroll
    for (int k = 0; k < NK; k++) { ps[k] = g_pos[t * NK + k]; Z += ps[k]; }
    float lz = logf(Z);
    float num = 0.f, den = 0.f;
    #pragma unroll
    for (int k = 0; k < NK; k++) {
        float lm = label_mask[t * NK + k];
        float p  = ps[k] + 1e-8f;
        num += lm * (logf(fmaxf(p, 1e-8f)) - lz);
        den += lm;
    }
    __shared__ float sn[32], sd[32];
    #pragma unroll
    for (int o = 16; o; o >>= 1) {
        num += __shfl_xor_sync(0xffffffffu, num, o);
        den += __shfl_xor_sync(0xffffffffu, den, o);
    }
    if ((t & 31) == 0) { sn[t >> 5] = num; sd[t >> 5] = den; }
    __syncthreads();
    if (t < 32) {
        num = sn[t]; den = sd[t];
        #pragma unroll
        for (int o = 16; o; o >>= 1) {
            num += __shfl_xor_sync(0xffffffffu, num, o);
            den += __shfl_xor_sync(0xffffffffu, den, o);
        }
        if (t == 0) out[0] = -num / (den + 1e-6f);
    }
}

// ---------------- launch ----------------
extern "C" void kernel_launch(void* const* d_in, const int* in_sizes, int n_in,
                              void* d_out, int out_size)
{
    const int*   indices    = (const int*)  d_in[0];
    const float* mask       = (const float*)d_in[1];
    const int*   labels     = (const int*)  d_in[2];
    const float* label_mask = (const float*)d_in[3];
    const int*   neg_idx    = (const int*)  d_in[4];
    const float* etab       = (const float*)d_in[5];
    const float* kern       = (const float*)d_in[6];
    const float* omega      = (const float*)d_in[7];
    const float* anchors    = (const float*)d_in[8];
    float* out = (float*)d_out;

    const double Cc = 2.0 + 1e-6;
    const double r2 = 1.4142135623730951;
    float s0 = (float)((2.0 - r2) / Cc);
    float s1 = (float)((2.0 + r2) / Cc);
    float t0 = sqrtf(2.0f * s0);
    float t1 = sqrtf(2.0f * s1);
    float w0 = (float)(((2.0 + r2) / 4.0) / Cc);
    float w1 = (float)(((2.0 - r2) / 4.0) / Cc);
    float invM = 1.0f / sqrtf(32.0f + 1e-6f);
    float c0 = sqrtf(fmaxf(w0, 1e-6f)) * invM;
    float c1 = sqrtf(fmaxf(w1, 1e-6f)) * invM;

    anch_kernel<<<1, 256>>>(anchors);
    query_feat_kernel<<<NB, 256>>>(indices, mask, etab, omega, s0, s1, t0, t1, c0, c1);
    w_feat_kernel<<<NW / WROWS, 256>>>(labels, neg_idx, kern, omega, s0, s1, t0, t1, c0, c1);
    pos_kernel<<<NPOS / 64, 256>>>();
    {
        dim3 grid(NB / QT, NSPLIT);
        score_neg_kernel<<<grid, 256>>>();
    }
    loss_kernel<<<1, NB>>>(label_mask, out);
}

// round 9
// speedup vs baseline: 1.5225x; 1.1406x over previous
#include <cuda_runtime.h>
#include <math.h>
#include <stdint.h>

// ---------------- problem constants ----------------
#define D_FULL   256
#define NHEAD    4
#define HDIM     64
#define NP       16
#define NM       32
#define NR       2
#define NB       1024
#define NL       128
#define NK       8
#define NNEG     2048
#define NPOS     (NB * NK)        /* 8192 */
#define NW       (NPOS + NNEG)    /* 10240 */
#define NUM_LABELS 131072
#define NF4      20               /* float4 feature groups per head: 4 poly + 16 prf */
#define WROWS    8                /* rows per w_feat block */
#define GCH      128              /* negs per G-partial block */
#define GSPLIT   (NNEG / GCH)     /* 16 */

// ---------------- device scratch ----------------
__device__ float  g_anchT[HDIM * NP];          // normalized anchors, transposed [d][p]
__device__ float4 g_Q4[NHEAD * NF4 * NB];      // query feats  [(h*20+f4)*NB + b]
__device__ float4 g_W4[NHEAD * NF4 * NW];      // W feats      [(h*20+f4)*NW + row]
__device__ float  g_pos[NPOS];
__device__ float4 g_Gpart4[GSPLIT * 4 * 256];  // [(s*4+h)*256 + p*16+i4]
__device__ float4 g_G4[4 * 256];               // [h*256 + p*16 + i4]
__device__ float  g_Zneg[NB];

// ---------------- anchors ----------------
__global__ void __launch_bounds__(256) anch_kernel(const float* __restrict__ anchors)
{
    __shared__ float inv[NP];
    int t = threadIdx.x;
    if (t < NP) {
        float s = 0.f;
        #pragma unroll 8
        for (int d = 0; d < HDIM; d++) {
            float v = anchors[t * HDIM + d];
            s = fmaf(v, v, s);
        }
        inv[t] = 1.f / sqrtf(s);
    }
    __syncthreads();
    for (int i = t; i < HDIM * NP; i += blockDim.x) {
        int p = i & (NP - 1);
        int d = i >> 4;
        g_anchT[i] = anchors[p * HDIM + d] * inv[p];
    }
}

// ---------------- per-row feature pipeline ----------------
// vcur = raw component for dim t. Global safe_normalize cancels under the
// per-head normalize. om = this thread's omega column (64 regs).
// Output address: out[row_off + f*fstride + c], f = global f4 index (0..79).
__device__ __forceinline__ void process_row(
    float vcur, int t, float* __restrict__ out, int row_off, int fstride,
    float4* s_x4, float* s_ws, const float* s_anch,
    const float (&om)[HDIM],
    float ss, float tt, float cc)
{
    float sq = vcur * vcur;
    #pragma unroll
    for (int o = 16; o; o >>= 1) sq += __shfl_xor_sync(0xffffffffu, sq, o);
    if ((t & 31) == 0) s_ws[t >> 5] = sq;
    __syncthreads();
    int hq = t >> 6;
    float n = sqrtf(s_ws[2 * hq] + s_ws[2 * hq + 1]);
    ((float*)s_x4)[t] = vcur / fmaxf(n, 1e-20f);
    __syncthreads();

    // PRF feature: thread t -> (r, hh, m)
    int r  = t >> 7;
    int hh = (t >> 5) & 3;
    int m  = t & 31;
    const float4* xh4 = s_x4 + hh * (HDIM / 4);
    float dotA = 0.f, dotB = 0.f;
    #pragma unroll
    for (int d4 = 0; d4 < HDIM / 4; d4++) {
        float4 x = xh4[d4];
        dotA = fmaf(x.x, om[4 * d4 + 0], dotA);
        dotB = fmaf(x.y, om[4 * d4 + 1], dotB);
        dotA = fmaf(x.z, om[4 * d4 + 2], dotA);
        dotB = fmaf(x.w, om[4 * d4 + 3], dotB);
    }
    float dot = (dotA + dotB) * 0.125f;            // omega / sqrt(64)
    float arg = fminf(fmaxf(dot * tt - ss, -20.f), 20.f);
    float pf  = expf(arg) * cc;
    int fin = 16 + r * NM + m;                     // within-head feature index
    out[row_off + (hh * NF4 + (fin >> 2)) * fstride + (fin & 3)] = pf;

    // poly feature: threads 0..63 -> (h2, p)
    if (t < 64) {
        int h2 = t >> 4, p = t & 15;
        const float* xh2 = (const float*)s_x4 + h2 * HDIM;
        float d2 = 0.f, d2b = 0.f;
        #pragma unroll
        for (int d = 0; d < HDIM; d += 2) {
            d2  = fmaf(xh2[d],     s_anch[d * NP + p],       d2);
            d2b = fmaf(xh2[d + 1], s_anch[(d + 1) * NP + p], d2b);
        }
        d2 += d2b;
        d2 = fminf(fmaxf(d2, -1.f), 1.f);
        out[row_off + (h2 * NF4 + (p >> 2)) * fstride + (p & 3)] = d2 * d2 * 0.25f;
    }
    __syncthreads();
}

// ---------------- queries: one block per query row ----------------
__global__ void __launch_bounds__(256) query_feat_kernel(
    const int* __restrict__ indices, const float* __restrict__ mask,
    const float* __restrict__ etab, const float* __restrict__ omega,
    float s0, float s1, float t0, float t1, float c0, float c1)
{
    __shared__ float4 s_x4[HDIM];
    __shared__ float  s_ws[8];
    __shared__ float  s_anch[HDIM * NP];
    __shared__ int    s_i[NL];
    __shared__ float  s_m[NL];
    int t = threadIdx.x, b = blockIdx.x;
    int r = t >> 7, hh = (t >> 5) & 3, m = t & 31;

    float om[HDIM];
    const float* omp = omega + ((size_t)(r * NHEAD + hh) * HDIM) * NM + m;
    #pragma unroll
    for (int d = 0; d < HDIM; d++) om[d] = omp[d * NM];
    for (int i = t; i < HDIM * NP; i += 256) s_anch[i] = g_anchT[i];
    float ss = r ? s1 : s0, tt = r ? t1 : t0, cc = r ? c1 : c0;

    if (t < NL) { s_i[t] = indices[b * NL + t]; s_m[t] = mask[b * NL + t]; }
    __syncthreads();
    float acc = 0.f;
    #pragma unroll 8
    for (int l = 0; l < NL; l++)
        acc = fmaf(s_m[l], etab[(size_t)s_i[l] * D_FULL + t], acc);
    // division by max(sum mask,1) cancels in per-head normalize
    process_row(acc, t, (float*)g_Q4, b * 4, NB * 4,
                s_x4, s_ws, s_anch, om, ss, tt, cc);
}

// ---------------- W subset: 8 rows per block, smem-staged coalesced writes ----------------
__global__ void __launch_bounds__(256) w_feat_kernel(
    const int* __restrict__ labels, const int* __restrict__ neg_idx,
    const float* __restrict__ kern, const float* __restrict__ omega,
    float s0, float s1, float t0, float t1, float c0, float c1)
{
    __shared__ float4 s_x4[HDIM];
    __shared__ float  s_ws[8];
    __shared__ float  s_anch[HDIM * NP];
    __shared__ float4 s_out[WROWS * 81];   // padded stride 81 (bank-spread)
    int t = threadIdx.x;
    int r = t >> 7, hh = (t >> 5) & 3, m = t & 31;

    float om[HDIM];
    const float* omp = omega + ((size_t)(r * NHEAD + hh) * HDIM) * NM + m;
    #pragma unroll
    for (int d = 0; d < HDIM; d++) om[d] = omp[d * NM];
    for (int i = t; i < HDIM * NP; i += 256) s_anch[i] = g_anchT[i];
    float ss = r ? s1 : s0, tt = r ? t1 : t0, cc = r ? c1 : c0;

    int row0 = blockIdx.x * WROWS;
    int c0i = (row0 < NPOS) ? (labels[row0] < 0 ? 0 : labels[row0]) : neg_idx[row0 - NPOS];
    float v = kern[(size_t)t * NUM_LABELS + c0i];
    __syncthreads();

    for (int rr = 0; rr < WROWS; rr++) {
        float vcur = v;
        if (rr + 1 < WROWS) {
            int nr = row0 + rr + 1;
            int c2 = (nr < NPOS) ? (labels[nr] < 0 ? 0 : labels[nr]) : neg_idx[nr - NPOS];
            v = kern[(size_t)t * NUM_LABELS + c2];
        }
        process_row(vcur, t, (float*)s_out, rr * 324, 4,
                    s_x4, s_ws, s_anch, om, ss, tt, cc);
    }
    // flush: 640 float4, coalesced 128B runs over consecutive rows
    #pragma unroll
    for (int k = 0; k < 3; k++) {
        int e = t + k * 256;
        if (e < NHEAD * NF4 * WROWS) {
            int f = e >> 3, rr = e & 7;
            g_W4[(size_t)f * NW + row0 + rr] = s_out[rr * 81 + f];
        }
    }
}

// ---------------- positives: 8 threads per row (4 heads x 2 parts) ----------------
__global__ void __launch_bounds__(256) pos_kernel()
{
    int t = threadIdx.x;
    int lane = t & 31;
    int rl = lane & 3;
    int part = (lane >> 2) & 1;
    int h = lane >> 3;
    int rowbase = (blockIdx.x * 8 + (t >> 5)) * 4;
    int rrow = rowbase + rl;
    int q = rrow >> 3;

    float dP = 0.f, dR = 0.f;
    if (part == 0) {
        #pragma unroll
        for (int f4 = 0; f4 < 4; f4++) {
            float4 w  = g_W4[(size_t)(h * NF4 + f4) * NW + rrow];
            float4 qv = g_Q4[(size_t)(h * NF4 + f4) * NB + q];
            dP = fmaf(qv.x, w.x, fmaf(qv.y, w.y, fmaf(qv.z, w.z, fmaf(qv.w, w.w, dP))));
        }
        #pragma unroll
        for (int f4 = 4; f4 < 12; f4++) {
            float4 w  = g_W4[(size_t)(h * NF4 + f4) * NW + rrow];
            float4 qv = g_Q4[(size_t)(h * NF4 + f4) * NB + q];
            dR = fmaf(qv.x, w.x, fmaf(qv.y, w.y, fmaf(qv.z, w.z, fmaf(qv.w, w.w, dR))));
        }
    } else {
        #pragma unroll
        for (int f4 = 12; f4 < 20; f4++) {
            float4 w  = g_W4[(size_t)(h * NF4 + f4) * NW + rrow];
            float4 qv = g_Q4[(size_t)(h * NF4 + f4) * NB + q];
            dR = fmaf(qv.x, w.x, fmaf(qv.y, w.y, fmaf(qv.z, w.z, fmaf(qv.w, w.w, dR))));
        }
    }
    dR += __shfl_xor_sync(0xffffffffu, dR, 4);   // combine the two dR halves
    float contrib = dP * dR;                      // part1 lanes: dP==0
    contrib += __shfl_xor_sync(0xffffffffu, contrib, 8);
    contrib += __shfl_xor_sync(0xffffffffu, contrib, 16);
    if (lane < 4) g_pos[rrow] = contrib;
}

// ---------------- G partials: G[h,p,i] = sum_negs Pw[n,h,p]*Rw[n,h,i] ----------------
__global__ void __launch_bounds__(256) gpart_kernel()
{
    __shared__ float4 sR4[GCH * 17];   // padded
    __shared__ float4 sP4[GCH * 5];    // padded
    int t = threadIdx.x;
    int h = blockIdx.x;
    int s = blockIdx.y;
    int n0 = NPOS + s * GCH;

    #pragma unroll
    for (int k = 0; k < 8; k++) {
        int e = t + k * 256;           // 2048: f4 = e>>7, n = e&127
        int f4 = e >> 7, n = e & 127;
        sR4[n * 17 + f4] = g_W4[(size_t)(h * NF4 + 4 + f4) * NW + n0 + n];
    }
    #pragma unroll
    for (int k = 0; k < 2; k++) {
        int e = t + k * 256;           // 512
        int f4 = e >> 7, n = e & 127;
        sP4[n * 5 + f4] = g_W4[(size_t)(h * NF4 + f4) * NW + n0 + n];
    }
    __syncthreads();

    int p = t >> 4, i4 = t & 15;
    const float* sPf = (const float*)sP4;
    float4 acc = make_float4(0.f, 0.f, 0.f, 0.f);
    #pragma unroll 4
    for (int n = 0; n < GCH; n++) {
        float  pv = sPf[n * 20 + p];
        float4 rv = sR4[n * 17 + i4];
        acc.x = fmaf(pv, rv.x, acc.x);
        acc.y = fmaf(pv, rv.y, acc.y);
        acc.z = fmaf(pv, rv.z, acc.z);
        acc.w = fmaf(pv, rv.w, acc.w);
    }
    g_Gpart4[(s * 4 + h) * 256 + t] = acc;
}

// ---------------- sum G partials ----------------
__global__ void __launch_bounds__(256) gsum_kernel()
{
    int j = blockIdx.x * 256 + threadIdx.x;   // < 1024
    float4 a = make_float4(0.f, 0.f, 0.f, 0.f);
    #pragma unroll
    for (int s = 0; s < GSPLIT; s++) {
        float4 v = g_Gpart4[s * 1024 + j];
        a.x += v.x; a.y += v.y; a.z += v.z; a.w += v.w;
    }
    g_G4[j] = a;
}

// ---------------- Z_neg: warp per query, bilinear contraction with G ----------------
__global__ void __launch_bounds__(256) zneg_kernel()
{
    int t = threadIdx.x;
    int b = blockIdx.x * 8 + (t >> 5);
    int lane = t & 31;
    float acc = 0.f;
    #pragma unroll
    for (int half = 0; half < 2; half++) {
        int e = lane + 32 * half;      // 0..63 -> (h,p)
        int h = e >> 4, p = e & 15;
        float ta = 0.f, tb = 0.f;
        #pragma unroll 8
        for (int i4 = 0; i4 < 16; i4++) {
            float4 qv = g_Q4[(size_t)(h * NF4 + 4 + i4) * NB + b];
            float4 gv = g_G4[(h * 16 + p) * 16 + i4];
            ta = fmaf(qv.x, gv.x, fmaf(qv.y, gv.y, ta));
            tb = fmaf(qv.z, gv.z, fmaf(qv.w, gv.w, tb));
        }
        float pq = ((const float*)g_Q4)[((size_t)(h * NF4 + (p >> 2)) * NB + b) * 4 + (p & 3)];
        acc = fmaf(pq, ta + tb, acc);
    }
    #pragma unroll
    for (int o = 16; o; o >>= 1) acc += __shfl_xor_sync(0xffffffffu, acc, o);
    if (lane == 0) g_Zneg[b] = acc;
}

// ---------------- final loss reduction ----------------
__global__ void __launch_bounds__(1024) loss_kernel(const float* __restrict__ label_mask,
                                                    float* __restrict__ out)
{
    int t = threadIdx.x;  // t == b
    // Z_b = Z_neg + sum pos + 2056*1e-8  (logsumexp(log x) == log(sum x))
    float Z = g_Zneg[t] + 2056.f * 1e-8f;
    float ps[NK];
    #pragma unroll
    for (int k = 0; k < NK; k++) { ps[k] = g_pos[t * NK + k]; Z += ps[k]; }
    float lz = logf(Z);
    float num = 0.f, den = 0.f;
    #pragma unroll
    for (int k = 0; k < NK; k++) {
        float lm = label_mask[t * NK + k];
        float p  = ps[k] + 1e-8f;
        num += lm * (logf(fmaxf(p, 1e-8f)) - lz);
        den += lm;
    }
    __shared__ float sn[32], sd[32];
    #pragma unroll
    for (int o = 16; o; o >>= 1) {
        num += __shfl_xor_sync(0xffffffffu, num, o);
        den += __shfl_xor_sync(0xffffffffu, den, o);
    }
    if ((t & 31) == 0) { sn[t >> 5] = num; sd[t >> 5] = den; }
    __syncthreads();
    if (t < 32) {
        num = sn[t]; den = sd[t];
        #pragma unroll
        for (int o = 16; o; o >>= 1) {
            num += __shfl_xor_sync(0xffffffffu, num, o);
            den += __shfl_xor_sync(0xffffffffu, den, o);
        }
        if (t == 0) out[0] = -num / (den + 1e-6f);
    }
}

// ---------------- launch ----------------
extern "C" void kernel_launch(void* const* d_in, const int* in_sizes, int n_in,
                              void* d_out, int out_size)
{
    const int*   indices    = (const int*)  d_in[0];
    const float* mask       = (const float*)d_in[1];
    const int*   labels     = (const int*)  d_in[2];
    const float* label_mask = (const float*)d_in[3];
    const int*   neg_idx    = (const int*)  d_in[4];
    const float* etab       = (const float*)d_in[5];
    const float* kern       = (const float*)d_in[6];
    const float* omega      = (const float*)d_in[7];
    const float* anchors    = (const float*)d_in[8];
    float* out = (float*)d_out;

    const double Cc = 2.0 + 1e-6;
    const double r2 = 1.4142135623730951;
    float s0 = (float)((2.0 - r2) / Cc);
    float s1 = (float)((2.0 + r2) / Cc);
    float t0 = sqrtf(2.0f * s0);
    float t1 = sqrtf(2.0f * s1);
    float w0 = (float)(((2.0 + r2) / 4.0) / Cc);
    float w1 = (float)(((2.0 - r2) / 4.0) / Cc);
    float invM = 1.0f / sqrtf(32.0f + 1e-6f);
    float c0 = sqrtf(fmaxf(w0, 1e-6f)) * invM;
    float c1 = sqrtf(fmaxf(w1, 1e-6f)) * invM;

    anch_kernel<<<1, 256>>>(anchors);
    query_feat_kernel<<<NB, 256>>>(indices, mask, etab, omega, s0, s1, t0, t1, c0, c1);
    w_feat_kernel<<<NW / WROWS, 256>>>(labels, neg_idx, kern, omega, s0, s1, t0, t1, c0, c1);
    pos_kernel<<<NPOS / 32, 256>>>();
    {
        dim3 grid(NHEAD, GSPLIT);
        gpart_kernel<<<grid, 256>>>();
    }
    gsum_kernel<<<4, 256>>>();
    zneg_kernel<<<NB / 8, 256>>>();
    loss_kernel<<<1, NB>>>(label_mask, out);
}

// round 11
// speedup vs baseline: 2.1284x; 1.3979x over previous
#include <cuda_runtime.h>
#include <math.h>
#include <stdint.h>

// ---------------- problem constants ----------------
#define D_FULL   256
#define NHEAD    4
#define HDIM     64
#define NP       16
#define NM       32
#define NR       2
#define NB       1024
#define NL       128
#define NK       8
#define NNEG     2048
#define NPOS     (NB * NK)        /* 8192 */
#define NW       (NPOS + NNEG)    /* 10240 */
#define NUM_LABELS 131072
#define NF4      20               /* float4 feature groups per head: 4 poly + 16 prf */
#define WROWS    8                /* rows per w_feat block */
#define GCH      128              /* negs per G-partial block */
#define GSPLIT   (NNEG / GCH)     /* 16 */

// ---------------- device scratch ----------------
__device__ float4 g_Q4[NHEAD * NF4 * NB];      // query feats  [(h*20+f4)*NB + b]
__device__ float4 g_W4[NHEAD * NF4 * NW];      // W feats      [(h*20+f4)*NW + row]
__device__ float  g_pos[NPOS];
__device__ float4 g_Gpart4[GSPLIT * 4 * 256];  // [(s*4+h)*256 + p*16+i4]
__device__ float  g_Zneg[NB];

// ---------------- inline anchor normalization (replaces anch_kernel) ----------------
__device__ __forceinline__ void load_anchors(const float* __restrict__ anchors,
                                             float* s_anch, float* s_ainv, int t)
{
    if (t < NP) {
        float s = 0.f;
        #pragma unroll 8
        for (int d = 0; d < HDIM; d++) {
            float v = anchors[t * HDIM + d];
            s = fmaf(v, v, s);
        }
        s_ainv[t] = 1.f / sqrtf(s);   // reference: raw norm, no eps
    }
    __syncthreads();
    for (int i = t; i < HDIM * NP; i += 256) {
        int p = i & (NP - 1);
        int d = i >> 4;
        s_anch[i] = anchors[p * HDIM + d] * s_ainv[p];
    }
    // consumer syncs before first s_anch use (inside process_row)
}

// ---------------- per-row feature pipeline ----------------
// vcur = raw component for dim t. Global safe_normalize cancels under the
// per-head normalize. om = this thread's omega column (64 regs).
__device__ __forceinline__ void process_row(
    float vcur, int t, float* __restrict__ out, int row_off, int fstride,
    float4* s_x4, float* s_ws, const float* s_anch,
    const float (&om)[HDIM],
    float ss, float tt, float cc)
{
    float sq = vcur * vcur;
    #pragma unroll
    for (int o = 16; o; o >>= 1) sq += __shfl_xor_sync(0xffffffffu, sq, o);
    if ((t & 31) == 0) s_ws[t >> 5] = sq;
    __syncthreads();
    int hq = t >> 6;
    float n = sqrtf(s_ws[2 * hq] + s_ws[2 * hq + 1]);
    ((float*)s_x4)[t] = vcur / fmaxf(n, 1e-20f);
    __syncthreads();

    // PRF feature: thread t -> (r, hh, m)
    int r  = t >> 7;
    int hh = (t >> 5) & 3;
    int m  = t & 31;
    const float4* xh4 = s_x4 + hh * (HDIM / 4);
    float dotA = 0.f, dotB = 0.f;
    #pragma unroll
    for (int d4 = 0; d4 < HDIM / 4; d4++) {
        float4 x = xh4[d4];
        dotA = fmaf(x.x, om[4 * d4 + 0], dotA);
        dotB = fmaf(x.y, om[4 * d4 + 1], dotB);
        dotA = fmaf(x.z, om[4 * d4 + 2], dotA);
        dotB = fmaf(x.w, om[4 * d4 + 3], dotB);
    }
    float dot = (dotA + dotB) * 0.125f;            // omega / sqrt(64)
    float arg = fminf(fmaxf(dot * tt - ss, -20.f), 20.f);
    float pf  = expf(arg) * cc;
    int fin = 16 + r * NM + m;                     // within-head feature index
    out[row_off + (hh * NF4 + (fin >> 2)) * fstride + (fin & 3)] = pf;

    // poly feature: threads 0..63 -> (h2, p)
    if (t < 64) {
        int h2 = t >> 4, p = t & 15;
        const float* xh2 = (const float*)s_x4 + h2 * HDIM;
        float d2 = 0.f, d2b = 0.f;
        #pragma unroll
        for (int d = 0; d < HDIM; d += 2) {
            d2  = fmaf(xh2[d],     s_anch[d * NP + p],       d2);
            d2b = fmaf(xh2[d + 1], s_anch[(d + 1) * NP + p], d2b);
        }
        d2 += d2b;
        d2 = fminf(fmaxf(d2, -1.f), 1.f);
        out[row_off + (h2 * NF4 + (p >> 2)) * fstride + (p & 3)] = d2 * d2 * 0.25f;
    }
    __syncthreads();
}

// ---------------- queries: one block per query row, float4 gather ----------------
__global__ void __launch_bounds__(256) query_feat_kernel(
    const int* __restrict__ indices, const float* __restrict__ mask,
    const float* __restrict__ etab, const float* __restrict__ omega,
    const float* __restrict__ anchors,
    float s0, float s1, float t0, float t1, float c0, float c1)
{
    __shared__ float4 s_x4[HDIM];
    __shared__ float  s_ws[8];
    __shared__ float  s_anch[HDIM * NP];
    __shared__ float  s_ainv[NP];
    __shared__ int    s_i[NL];
    __shared__ float  s_m[NL];
    __shared__ float4 s_red[256];
    int t = threadIdx.x, b = blockIdx.x;
    int r = t >> 7, hh = (t >> 5) & 3, m = t & 31;

    float om[HDIM];
    const float* omp = omega + ((size_t)(r * NHEAD + hh) * HDIM) * NM + m;
    #pragma unroll
    for (int d = 0; d < HDIM; d++) om[d] = omp[d * NM];
    load_anchors(anchors, s_anch, s_ainv, t);
    float ss = r ? s1 : s0, tt = r ? t1 : t0, cc = r ? c1 : c0;

    if (t < NL) { s_i[t] = indices[b * NL + t]; s_m[t] = mask[b * NL + t]; }
    __syncthreads();

    // float4 gather: thread t -> dim-quad (t&63), label slice (t>>6) of 4
    int q4 = t & 63, ls = t >> 6;
    const float4* etab4 = (const float4*)etab;
    float4 a = make_float4(0.f, 0.f, 0.f, 0.f);
    #pragma unroll 8
    for (int l = ls; l < NL; l += 4) {
        float mv = s_m[l];
        float4 e = etab4[(size_t)s_i[l] * (D_FULL / 4) + q4];
        a.x = fmaf(mv, e.x, a.x);
        a.y = fmaf(mv, e.y, a.y);
        a.z = fmaf(mv, e.z, a.z);
        a.w = fmaf(mv, e.w, a.w);
    }
    s_red[t] = a;
    __syncthreads();
    if (t < 64) {
        float4 r0 = s_red[t], r1 = s_red[64 + t], r2 = s_red[128 + t], r3 = s_red[192 + t];
        // reuse s_red[0..63] as the summed raw row
        s_red[t] = make_float4((r0.x + r1.x) + (r2.x + r3.x),
                               (r0.y + r1.y) + (r2.y + r3.y),
                               (r0.z + r1.z) + (r2.z + r3.z),
                               (r0.w + r1.w) + (r2.w + r3.w));
    }
    __syncthreads();
    float acc = ((const float*)s_red)[t];
    // division by max(sum mask,1) cancels in per-head normalize
    process_row(acc, t, (float*)g_Q4, b * 4, NB * 4,
                s_x4, s_ws, s_anch, om, ss, tt, cc);
}

// ---------------- W subset: 8 rows per block, all gathers issued upfront ----------------
__global__ void __launch_bounds__(256) w_feat_kernel(
    const int* __restrict__ labels, const int* __restrict__ neg_idx,
    const float* __restrict__ kern, const float* __restrict__ omega,
    const float* __restrict__ anchors,
    float s0, float s1, float t0, float t1, float c0, float c1)
{
    __shared__ float4 s_x4[HDIM];
    __shared__ float  s_ws[8];
    __shared__ float  s_anch[HDIM * NP];
    __shared__ float  s_ainv[NP];
    __shared__ float4 s_out[WROWS * 81];   // padded stride 81
    int t = threadIdx.x;
    int r = t >> 7, hh = (t >> 5) & 3, m = t & 31;

    float om[HDIM];
    const float* omp = omega + ((size_t)(r * NHEAD + hh) * HDIM) * NM + m;
    #pragma unroll
    for (int d = 0; d < HDIM; d++) om[d] = omp[d * NM];
    load_anchors(anchors, s_anch, s_ainv, t);
    float ss = r ? s1 : s0, tt = r ? t1 : t0, cc = r ? c1 : c0;

    int row0 = blockIdx.x * WROWS;
    // all 8 scattered gathers in flight together (MLP 8)
    float v[WROWS];
    #pragma unroll
    for (int rr = 0; rr < WROWS; rr++) {
        int row = row0 + rr;
        int col = (row < NPOS) ? (labels[row] < 0 ? 0 : labels[row]) : neg_idx[row - NPOS];
        v[rr] = kern[(size_t)t * NUM_LABELS + col];
    }
    __syncthreads();

    #pragma unroll
    for (int rr = 0; rr < WROWS; rr++)
        process_row(v[rr], t, (float*)s_out, rr * 324, 4,
                    s_x4, s_ws, s_anch, om, ss, tt, cc);

    // flush: 640 float4, coalesced over consecutive rows
    #pragma unroll
    for (int k = 0; k < 3; k++) {
        int e = t + k * 256;
        if (e < NHEAD * NF4 * WROWS) {
            int f = e >> 3, rr = e & 7;
            g_W4[(size_t)f * NW + row0 + rr] = s_out[rr * 81 + f];
        }
    }
}

// ---------------- positives: one thread per (row, head), deep MLP ----------------
__global__ void __launch_bounds__(128) pos_kernel()
{
    int gid = blockIdx.x * 128 + threadIdx.x;   // 32768 = 8192 rows * 4 heads
    int rrow = gid >> 2;
    int h = gid & 3;
    int q = rrow >> 3;
    int lane = threadIdx.x & 31;

    float dP = 0.f;
    #pragma unroll
    for (int f4 = 0; f4 < 4; f4++) {
        float4 w  = g_W4[(size_t)(h * NF4 + f4) * NW + rrow];
        float4 qv = g_Q4[(size_t)(h * NF4 + f4) * NB + q];
        dP = fmaf(qv.x, w.x, fmaf(qv.y, w.y, fmaf(qv.z, w.z, fmaf(qv.w, w.w, dP))));
    }
    float dR = 0.f;
    #pragma unroll
    for (int f4 = 4; f4 < NF4; f4++) {
        float4 w  = g_W4[(size_t)(h * NF4 + f4) * NW + rrow];
        float4 qv = g_Q4[(size_t)(h * NF4 + f4) * NB + q];
        dR = fmaf(qv.x, w.x, fmaf(qv.y, w.y, fmaf(qv.z, w.z, fmaf(qv.w, w.w, dR))));
    }
    float c = dP * dR;                 // per-head contribution
    c += __shfl_xor_sync(0xffffffffu, c, 1);
    c += __shfl_xor_sync(0xffffffffu, c, 2);
    if ((lane & 3) == 0) g_pos[rrow] = c;
}

// ---------------- G partials: G[h,p,i] = sum_negs Pw[n,h,p]*Rw[n,h,i] ----------------
__global__ void __launch_bounds__(256) gpart_kernel()
{
    __shared__ float4 sR4[GCH * 17];   // padded
    __shared__ float4 sP4[GCH * 5];    // padded
    int t = threadIdx.x;
    int h = blockIdx.x;
    int s = blockIdx.y;
    int n0 = NPOS + s * GCH;

    #pragma unroll
    for (int k = 0; k < 8; k++) {
        int e = t + k * 256;
        int f4 = e >> 7, n = e & 127;
        sR4[n * 17 + f4] = g_W4[(size_t)(h * NF4 + 4 + f4) * NW + n0 + n];
    }
    #pragma unroll
    for (int k = 0; k < 2; k++) {
        int e = t + k * 256;
        int f4 = e >> 7, n = e & 127;
        sP4[n * 5 + f4] = g_W4[(size_t)(h * NF4 + f4) * NW + n0 + n];
    }
    __syncthreads();

    int p = t >> 4, i4 = t & 15;
    const float* sPf = (const float*)sP4;
    float4 acc = make_float4(0.f, 0.f, 0.f, 0.f);
    #pragma unroll 4
    for (int n = 0; n < GCH; n++) {
        float  pv = sPf[n * 20 + p];
        float4 rv = sR4[n * 17 + i4];
        acc.x = fmaf(pv, rv.x, acc.x);
        acc.y = fmaf(pv, rv.y, acc.y);
        acc.z = fmaf(pv, rv.z, acc.z);
        acc.w = fmaf(pv, rv.w, acc.w);
    }
    g_Gpart4[(s * 4 + h) * 256 + t] = acc;
}

// ---------------- Z_neg: sum G partials in smem, then warp-per-query contraction ----------------
__global__ void __launch_bounds__(256) zneg_kernel()
{
    __shared__ float4 sG[64 * 17];     // [(h*16+p)*17 + i4], padded
    int t = threadIdx.x;

    for (int j = t; j < 1024; j += 256) {
        float4 a = make_float4(0.f, 0.f, 0.f, 0.f);
        #pragma unroll
        for (int s = 0; s < GSPLIT; s++) {
            float4 v = g_Gpart4[s * 1024 + j];
            a.x += v.x; a.y += v.y; a.z += v.z; a.w += v.w;
        }
        sG[(j >> 4) * 17 + (j & 15)] = a;
    }
    __syncthreads();

    int b = blockIdx.x * 8 + (t >> 5);
    int lane = t & 31;
    float acc = 0.f;
    #pragma unroll
    for (int half = 0; half < 2; half++) {
        int e = lane + 32 * half;      // 0..63 -> (h,p)
        int h = e >> 4, p = e & 15;
        float ta = 0.f, tb = 0.f;
        #pragma unroll 8
        for (int i4 = 0; i4 < 16; i4++) {
            float4 qv = g_Q4[(size_t)(h * NF4 + 4 + i4) * NB + b];
            float4 gv = sG[(h * 16 + p) * 17 + i4];
            ta = fmaf(qv.x, gv.x, fmaf(qv.y, gv.y, ta));
            tb = fmaf(qv.z, gv.z, fmaf(qv.w, gv.w, tb));
        }
        float pq = ((const float*)g_Q4)[((size_t)(h * NF4 + (p >> 2)) * NB + b) * 4 + (p & 3)];
        acc = fmaf(pq, ta + tb, acc);
    }
    #pragma unroll
    for (int o = 16; o; o >>= 1) acc += __shfl_xor_sync(0xffffffffu, acc, o);
    if (lane == 0) g_Zneg[b] = acc;
}

// ---------------- final loss reduction ----------------
__global__ void __launch_bounds__(1024) loss_kernel(const float* __restrict__ label_mask,
                                                    float* __restrict__ out)
{
    int t = threadIdx.x;  // t == b
    // Z_b = Z_neg + sum pos + 2056*1e-8  (logsumexp(log x) == log(sum x))
    float Z = g_Zneg[t] + 2056.f * 1e-8f;
    float ps[NK];
    #pragma unroll
    for (int k = 0; k < NK; k++) { ps[k] = g_pos[t * NK + k]; Z += ps[k]; }
    float lz = logf(Z);
    float num = 0.f, den = 0.f;
    #pragma unroll
    for (int k = 0; k < NK; k++) {
        float lm = label_mask[t * NK + k];
        float p  = ps[k] + 1e-8f;
        num += lm * (logf(fmaxf(p, 1e-8f)) - lz);
        den += lm;
    }
    __shared__ float sn[32], sd[32];
    #pragma unroll
    for (int o = 16; o; o >>= 1) {
        num += __shfl_xor_sync(0xffffffffu, num, o);
        den += __shfl_xor_sync(0xffffffffu, den, o);
    }
    if ((t & 31) == 0) { sn[t >> 5] = num; sd[t >> 5] = den; }
    __syncthreads();
    if (t < 32) {
        num = sn[t]; den = sd[t];
        #pragma unroll
        for (int o = 16; o; o >>= 1) {
            num += __shfl_xor_sync(0xffffffffu, num, o);
            den += __shfl_xor_sync(0xffffffffu, den, o);
        }
        if (t == 0) out[0] = -num / (den + 1e-6f);
    }
}

// ---------------- launch ----------------
extern "C" void kernel_launch(void* const* d_in, const int* in_sizes, int n_in,
                              void* d_out, int out_size)
{
    const int*   indices    = (const int*)  d_in[0];
    const float* mask       = (const float*)d_in[1];
    const int*   labels     = (const int*)  d_in[2];
    const float* label_mask = (const float*)d_in[3];
    const int*   neg_idx    = (const int*)  d_in[4];
    const float* etab       = (const float*)d_in[5];
    const float* kern       = (const float*)d_in[6];
    const float* omega      = (const float*)d_in[7];
    const float* anchors    = (const float*)d_in[8];
    float* out = (float*)d_out;

    const double Cc = 2.0 + 1e-6;
    const double r2 = 1.4142135623730951;
    float s0 = (float)((2.0 - r2) / Cc);
    float s1 = (float)((2.0 + r2) / Cc);
    float t0 = sqrtf(2.0f * s0);
    float t1 = sqrtf(2.0f * s1);
    float w0 = (float)(((2.0 + r2) / 4.0) / Cc);
    float w1 = (float)(((2.0 - r2) / 4.0) / Cc);
    float invM = 1.0f / sqrtf(32.0f + 1e-6f);
    float c0 = sqrtf(fmaxf(w0, 1e-6f)) * invM;
    float c1 = sqrtf(fmaxf(w1, 1e-6f)) * invM;

    query_feat_kernel<<<NB, 256>>>(indices, mask, etab, omega, anchors,
                                   s0, s1, t0, t1, c0, c1);
    w_feat_kernel<<<NW / WROWS, 256>>>(labels, neg_idx, kern, omega, anchors,
                                       s0, s1, t0, t1, c0, c1);
    pos_kernel<<<NPOS * 4 / 128, 128>>>();
    {
        dim3 grid(NHEAD, GSPLIT);
        gpart_kernel<<<grid, 256>>>();
    }
    zneg_kernel<<<NB / 8, 256>>>();
    loss_kernel<<<1, NB>>>(label_mask, out);
}